// round 2
// baseline (speedup 1.0000x reference)
#include <cuda_runtime.h>
#include <math.h>

#define Bq   2
#define Lq   1024
#define Hq   16
#define Dq   64
#define HIDq 1024

// ---------------- scratch (static device globals; no runtime alloc) ----------
__device__ float g_qkv[Bq * Lq * 3 * Hq * Dq];                  // (B,L,3,H,D)  25 MB
__device__ float g_q[Bq * Hq * Lq * Dq];                        // (B,H,L,D)     8 MB
__device__ float g_k[Bq * Hq * Lq * Dq];
__device__ float g_v[Bq * Hq * Lq * Dq];
__device__ float g_sc[(long long)Bq * Hq * Lq * Lq];            // (B,H,L,L)   134 MB
__device__ float g_attn[Bq * Lq * Hq * Dq];                     // (B,L,H*D)     8 MB

// ---------------- generic tiled fp32 GEMM -----------------------------------
// C = alpha * A @ B   (TRANSB: B stored (N,K) row-major -> C = A @ B^T)
// CAUSAL: skip blocks fully above the diagonal.
// CMODE : batched C base = (bz>>4)*L*HID + (bz&15)*D  (for (B,L,H*D) output)
template <int TRANSB, int CAUSAL, int CMODE>
__global__ __launch_bounds__(256)
void sgemm_kernel(const float* __restrict__ A, const float* __restrict__ Bm,
                  float* __restrict__ C,
                  int M, int N, int K, int lda, int ldb, int ldc,
                  long long sA, long long sB, long long sC, float alpha)
{
    int bz = blockIdx.z;
    A  += (long long)bz * sA;
    Bm += (long long)bz * sB;
    if (CMODE) C += (long long)(bz >> 4) * ((long long)Lq * HIDq) + (long long)(bz & 15) * Dq;
    else       C += (long long)bz * sC;

    int i0 = blockIdx.y * 64, j0 = blockIdx.x * 64;
    if (CAUSAL && j0 > i0 + 63) return;

    __shared__ float As[16][64];
    __shared__ float Bs[16][64];

    int tid = threadIdx.x;
    int tx = tid & 15, ty = tid >> 4;

    float acc[4][4] = {};

    for (int k0 = 0; k0 < K; k0 += 16) {
        #pragma unroll
        for (int t = tid; t < 1024; t += 256) {
            int m = t >> 4, kk = t & 15;
            As[kk][m] = A[(long long)(i0 + m) * lda + k0 + kk];
        }
        if (TRANSB) {
            #pragma unroll
            for (int t = tid; t < 1024; t += 256) {
                int n = t >> 4, kk = t & 15;
                Bs[kk][n] = Bm[(long long)(j0 + n) * ldb + k0 + kk];
            }
        } else {
            #pragma unroll
            for (int t = tid; t < 1024; t += 256) {
                int kk = t >> 6, n = t & 63;
                Bs[kk][n] = Bm[(long long)(k0 + kk) * ldb + j0 + n];
            }
        }
        __syncthreads();

        #pragma unroll
        for (int kk = 0; kk < 16; kk++) {
            float4 a4 = *(const float4*)&As[kk][ty * 4];
            float4 b4 = *(const float4*)&Bs[kk][tx * 4];
            float a[4] = {a4.x, a4.y, a4.z, a4.w};
            float b[4] = {b4.x, b4.y, b4.z, b4.w};
            #pragma unroll
            for (int x = 0; x < 4; x++)
                #pragma unroll
                for (int y = 0; y < 4; y++)
                    acc[x][y] += a[x] * b[y];
        }
        __syncthreads();
    }

    #pragma unroll
    for (int x = 0; x < 4; x++)
        #pragma unroll
        for (int y = 0; y < 4; y++)
            C[(long long)(i0 + ty * 4 + x) * ldc + j0 + tx * 4 + y] = alpha * acc[x][y];
}

// ---------------- qkv split + RoPE ------------------------------------------
__global__ void rope_split_kernel(const float* __restrict__ qkv,
                                  float* __restrict__ q, float* __restrict__ k,
                                  float* __restrict__ v)
{
    int idx = blockIdx.x * blockDim.x + threadIdx.x;   // over B*H*L*D = 2M
    if (idx >= Bq * Hq * Lq * Dq) return;
    int d = idx & 63;
    int l = (idx >> 6) & 1023;
    int h = (idx >> 16) & 15;
    int b = idx >> 20;

    long long base = ((long long)(b * Lq + l) * 3) * (Hq * Dq) + h * Dq;
    float qa = qkv[base + d];
    float ka = qkv[base + Hq * Dq + d];
    float vv = qkv[base + 2 * Hq * Dq + d];
    int dp = (d < 32) ? d + 32 : d - 32;
    float qb = qkv[base + dp];
    float kb = qkv[base + Hq * Dq + dp];

    int fi = (d < 32) ? d : d - 32;
    float ang = (float)l * powf(10000.0f, -(float)fi / 32.0f);
    float c = cosf(ang), s = sinf(ang);
    float sgn = (d < 32) ? -1.0f : 1.0f;

    long long o = ((long long)(b * Hq + h) * Lq + l) * Dq + d;
    q[o] = qa * c + sgn * qb * s;
    k[o] = ka * c + sgn * kb * s;
    v[o] = vv;
}

// ---------------- fused kerple + DAPE MLP + causal softmax ------------------
// One block per (b, i). 256 threads, 4 j's per thread (j = tid + 256*m).
__global__ __launch_bounds__(256, 1)
void dape_softmax_kernel(float* __restrict__ scores,   // (B,H,L,L), in/out
                         const float* __restrict__ w1, const float* __restrict__ b1,
                         const float* __restrict__ w2, const float* __restrict__ b2,
                         const float* __restrict__ log_p, const float* __restrict__ log_a)
{
    __shared__ float s_w1[32 * 32];   // transposed: [o][in]
    __shared__ float s_w2[16 * 32];   // transposed: [h][o]
    __shared__ float s_b1[32], s_b2[16], s_p[16], s_a[16];
    __shared__ float s_red[16 * 8];
    __shared__ float s_bc[16];

    int tid = threadIdx.x;
    int i = blockIdx.x & (Lq - 1);
    int b = blockIdx.x >> 10;

    for (int t = tid; t < 1024; t += 256) {
        int in = t >> 5, o = t & 31;
        s_w1[o * 32 + in] = w1[in * 32 + o];
    }
    for (int t = tid; t < 512; t += 256) {
        int o = t >> 4, h = t & 15;
        s_w2[h * 32 + o] = w2[o * 16 + h];
    }
    if (tid < 32) s_b1[tid] = b1[tid];
    if (tid < 16) {
        s_b2[tid] = b2[tid];
        s_p[tid] = log1pf(expf(log_p[tid]));
        s_a[tid] = log1pf(expf(log_a[tid]));
    }
    __syncthreads();

    long long base0 = (long long)b * (Hq * Lq * Lq) + (long long)i * Lq;
    float fin[4][16];

    #pragma unroll
    for (int m = 0; m < 4; m++) {
        int j = tid + m * 256;
        if (j <= i) {
            float comb[32];
            float dist = (float)(i - j);
            #pragma unroll
            for (int h = 0; h < 16; h++) {
                comb[h]      = scores[base0 + (long long)h * (Lq * Lq) + j];
                comb[16 + h] = -s_p[h] * log1pf(s_a[h] * dist);
            }
            float hid[32];
            #pragma unroll
            for (int o = 0; o < 32; o++) {
                float acc = s_b1[o];
                #pragma unroll
                for (int in = 0; in < 32; in++) acc += comb[in] * s_w1[o * 32 + in];
                hid[o] = 0.5f * acc * (1.0f + erff(acc * 0.70710678118654752f));
            }
            #pragma unroll
            for (int h = 0; h < 16; h++) {
                float acc = s_b2[h];
                #pragma unroll
                for (int o = 0; o < 32; o++) acc += hid[o] * s_w2[h * 32 + o];
                fin[m][h] = comb[h] + comb[16 + h] + acc;
            }
        } else {
            #pragma unroll
            for (int h = 0; h < 16; h++) fin[m][h] = -INFINITY;
        }
    }

    // --- per-head block max ---
    float mx[16];
    #pragma unroll
    for (int h = 0; h < 16; h++) {
        float vmax = fin[0][h];
        #pragma unroll
        for (int m = 1; m < 4; m++) vmax = fmaxf(vmax, fin[m][h]);
        #pragma unroll
        for (int off = 16; off > 0; off >>= 1)
            vmax = fmaxf(vmax, __shfl_xor_sync(0xffffffffu, vmax, off));
        if ((tid & 31) == 0) s_red[h * 8 + (tid >> 5)] = vmax;
    }
    __syncthreads();
    if (tid < 16) {
        float vv = s_red[tid * 8];
        #pragma unroll
        for (int w = 1; w < 8; w++) vv = fmaxf(vv, s_red[tid * 8 + w]);
        s_bc[tid] = vv;
    }
    __syncthreads();
    #pragma unroll
    for (int h = 0; h < 16; h++) mx[h] = s_bc[h];
    __syncthreads();

    // --- exp + per-head block sum ---
    float sm[16];
    #pragma unroll
    for (int h = 0; h < 16; h++) sm[h] = 0.0f;
    #pragma unroll
    for (int m = 0; m < 4; m++)
        #pragma unroll
        for (int h = 0; h < 16; h++) {
            float e = expf(fin[m][h] - mx[h]);   // expf(-inf) = 0 for masked j
            fin[m][h] = e;
            sm[h] += e;
        }
    #pragma unroll
    for (int h = 0; h < 16; h++) {
        float vs = sm[h];
        #pragma unroll
        for (int off = 16; off > 0; off >>= 1)
            vs += __shfl_xor_sync(0xffffffffu, vs, off);
        if ((tid & 31) == 0) s_red[h * 8 + (tid >> 5)] = vs;
    }
    __syncthreads();
    if (tid < 16) {
        float vv = 0.0f;
        #pragma unroll
        for (int w = 0; w < 8; w++) vv += s_red[tid * 8 + w];
        s_bc[tid] = 1.0f / vv;
    }
    __syncthreads();

    // --- write normalized weights (zeros above diagonal) ---
    #pragma unroll
    for (int m = 0; m < 4; m++) {
        int j = tid + m * 256;
        #pragma unroll
        for (int h = 0; h < 16; h++)
            scores[base0 + (long long)h * (Lq * Lq) + j] = fin[m][h] * s_bc[h];
    }
}

// ---------------- launch ----------------------------------------------------
extern "C" void kernel_launch(void* const* d_in, const int* in_sizes, int n_in,
                              void* d_out, int out_size)
{
    const float* x     = (const float*)d_in[0];
    const float* w_qkv = (const float*)d_in[1];
    const float* w_o   = (const float*)d_in[2];
    const float* log_p = (const float*)d_in[3];
    const float* log_a = (const float*)d_in[4];
    const float* w1    = (const float*)d_in[5];
    const float* b1    = (const float*)d_in[6];
    const float* w2    = (const float*)d_in[7];
    const float* b2    = (const float*)d_in[8];
    float* out = (float*)d_out;
    (void)in_sizes; (void)n_in; (void)out_size;

    float *qkv, *q, *k, *v, *sc, *attn;
    cudaGetSymbolAddress((void**)&qkv,  g_qkv);
    cudaGetSymbolAddress((void**)&q,    g_q);
    cudaGetSymbolAddress((void**)&k,    g_k);
    cudaGetSymbolAddress((void**)&v,    g_v);
    cudaGetSymbolAddress((void**)&sc,   g_sc);
    cudaGetSymbolAddress((void**)&attn, g_attn);

    const int M  = Bq * Lq;          // 2048
    const int TH = 3 * Hq * Dq;      // 3072

    // 1) qkv = x @ w_qkv : (2048 x 3072 x 1024)
    sgemm_kernel<0, 0, 0><<<dim3(TH / 64, M / 64, 1), 256>>>(
        x, w_qkv, qkv, M, TH, HIDq, HIDq, TH, TH, 0, 0, 0, 1.0f);

    // 2) split + RoPE -> g_q, g_k, g_v in (B,H,L,D)
    rope_split_kernel<<<(Bq * Hq * Lq * Dq) / 256, 256>>>(qkv, q, k, v);

    // 3) scores = (q @ k^T) / sqrt(D), batched over B*H=32, causal block skip
    sgemm_kernel<1, 1, 0><<<dim3(Lq / 64, Lq / 64, Bq * Hq), 256>>>(
        q, k, sc, Lq, Lq, Dq, Dq, Dq, Lq,
        (long long)Lq * Dq, (long long)Lq * Dq, (long long)Lq * Lq, 0.125f);

    // 4) fused kerple + DAPE MLP + causal softmax (in-place on g_sc)
    dape_softmax_kernel<<<Bq * Lq, 256>>>(sc, w1, b1, w2, b2, log_p, log_a);

    // 5) attn(B,L,H*D) = weights @ v, batched; CMODE writes transposed layout
    sgemm_kernel<0, 0, 1><<<dim3(1, Lq / 64, Bq * Hq), 256>>>(
        sc, v, attn, Lq, Dq, Lq, Lq, Dq, HIDq,
        (long long)Lq * Lq, (long long)Lq * Dq, 0, 1.0f);

    // 6) out = attn @ w_o : (2048 x 1024 x 1024)
    sgemm_kernel<0, 0, 0><<<dim3(HIDq / 64, M / 64, 1), 256>>>(
        attn, w_o, out, M, HIDq, HIDq, HIDq, HIDq, HIDq, 0, 0, 0, 1.0f);
}

// round 4
// speedup vs baseline: 1.6013x; 1.6013x over previous
#include <cuda_runtime.h>
#include <cuda_bf16.h>
#include <math.h>

#define Bq   2
#define Lq   1024
#define Hq   16
#define Dq   64
#define HIDq 1024

// ---------------- scratch (static device globals; no runtime alloc) ----------
__device__ float g_qkv[Bq * Lq * 3 * Hq * Dq];                  // (B,L,3,H,D)
__device__ float g_q[Bq * Hq * Lq * Dq];                        // (B,H,L,D)
__device__ float g_k[Bq * Hq * Lq * Dq];
__device__ float g_v[Bq * Hq * Lq * Dq];
__device__ float g_sc[(long long)Bq * Hq * Lq * Lq];            // (B,H,L,L)
__device__ float g_attn[Bq * Lq * Hq * Dq];                     // (B,L,H*D)

// bf16 split-precision operand buffers
__device__ __nv_bfloat16 g_xhi[2048 * 1024];
__device__ __nv_bfloat16 g_xlo[2048 * 1024];
__device__ __nv_bfloat16 g_wqkvT_hi[3072 * 1024];
__device__ __nv_bfloat16 g_wqkvT_lo[3072 * 1024];
__device__ __nv_bfloat16 g_ahi[2048 * 1024];
__device__ __nv_bfloat16 g_alo[2048 * 1024];
__device__ __nv_bfloat16 g_woT_hi[1024 * 1024];
__device__ __nv_bfloat16 g_woT_lo[1024 * 1024];

// DAPE precomputed tables
__device__ float g_kc[32 * 1024];     // [o][dist]
__device__ float g_ktab[16 * 1024];   // [h][dist]

// ======================= bf16 split tensor-core GEMM ========================
// C(M,N) fp32 = Ahi/lo(M,K) x Bhi/lo(N,K)^T, split precision: hh + hl + lh.
#define BM 128
#define BN 128
#define BK 32

__device__ __forceinline__ void ldm_x4(unsigned r[4], unsigned addr) {
    asm volatile("ldmatrix.sync.aligned.m8n8.x4.shared.b16 {%0,%1,%2,%3}, [%4];"
        : "=r"(r[0]), "=r"(r[1]), "=r"(r[2]), "=r"(r[3]) : "r"(addr));
}
__device__ __forceinline__ void mma16816(float c[4], const unsigned a[4],
                                         unsigned b0, unsigned b1) {
    asm volatile("mma.sync.aligned.m16n8k16.row.col.f32.bf16.bf16.f32 "
        "{%0,%1,%2,%3},{%4,%5,%6,%7},{%8,%9},{%0,%1,%2,%3};"
        : "+f"(c[0]), "+f"(c[1]), "+f"(c[2]), "+f"(c[3])
        : "r"(a[0]), "r"(a[1]), "r"(a[2]), "r"(a[3]), "r"(b0), "r"(b1));
}
__device__ __forceinline__ void cp16(unsigned saddr, const void* g) {
    asm volatile("cp.async.cg.shared.global [%0], [%1], 16;\n" :: "r"(saddr), "l"(g));
}

__global__ __launch_bounds__(256)
void hgemm_split_kernel(const __nv_bfloat16* __restrict__ Ahi,
                        const __nv_bfloat16* __restrict__ Alo,
                        const __nv_bfloat16* __restrict__ Bhi,
                        const __nv_bfloat16* __restrict__ Blo,
                        float* __restrict__ C, int M, int N, int K)
{
    extern __shared__ __nv_bfloat16 smem[];
    // stage layout (bytes): Ahi[0,8192) Alo[8192,16384) Bhi[16384,24576) Blo[24576,32768)
    const int tid = threadIdx.x;
    const int wid = tid >> 5, lane = tid & 31;
    const int wm = wid >> 2, wn = wid & 3;                 // 2 x 4 warp grid
    const int bi = blockIdx.y * BM, bj = blockIdx.x * BN;
    const unsigned sgen = (unsigned)__cvta_generic_to_shared(smem);

    float acc[4][4][4];
    #pragma unroll
    for (int a = 0; a < 4; a++)
        #pragma unroll
        for (int b = 0; b < 4; b++)
            #pragma unroll
            for (int c = 0; c < 4; c++) acc[a][b][c] = 0.f;

    auto load_stage = [&](int stage, int kt) {
        int k0 = kt * BK;
        unsigned sb = sgen + stage * 32768;
        #pragma unroll
        for (int rep = 0; rep < 2; rep++) {
            int c = tid + rep * 256;
            int row = c >> 2, kc = c & 3;
            unsigned swc = (unsigned)(kc ^ ((row >> 1) & 3));
            unsigned so = sb + (unsigned)row * 64u + swc * 16u;
            const __nv_bfloat16* gah = Ahi + (size_t)(bi + row) * K + k0 + kc * 8;
            const __nv_bfloat16* gal = Alo + (size_t)(bi + row) * K + k0 + kc * 8;
            const __nv_bfloat16* gbh = Bhi + (size_t)(bj + row) * K + k0 + kc * 8;
            const __nv_bfloat16* gbl = Blo + (size_t)(bj + row) * K + k0 + kc * 8;
            cp16(so,          gah);
            cp16(so +  8192u, gal);
            cp16(so + 16384u, gbh);
            cp16(so + 24576u, gbl);
        }
    };

    auto compute_stage = [&](int stage) {
        unsigned sb = sgen + stage * 32768;
        #pragma unroll
        for (int ks = 0; ks < 2; ks++) {
            int r = lane & 15;
            int cc = ks * 2 + (lane >> 4);
            unsigned a_hi[4][4], a_lo[4][4];
            #pragma unroll
            for (int mt = 0; mt < 4; mt++) {
                int row = wm * 64 + mt * 16 + r;
                unsigned swc = (unsigned)(cc ^ ((row >> 1) & 3));
                unsigned addr = sb + (unsigned)row * 64u + swc * 16u;
                ldm_x4(a_hi[mt], addr);
                ldm_x4(a_lo[mt], addr + 8192u);
            }
            unsigned b_hi[2][4], b_lo[2][4];
            #pragma unroll
            for (int bt = 0; bt < 2; bt++) {
                int row = wn * 32 + bt * 16 + r;
                unsigned swc = (unsigned)(cc ^ ((row >> 1) & 3));
                unsigned addr = sb + 16384u + (unsigned)row * 64u + swc * 16u;
                ldm_x4(b_hi[bt], addr);
                ldm_x4(b_lo[bt], addr + 8192u);
            }
            #pragma unroll
            for (int mt = 0; mt < 4; mt++)
                #pragma unroll
                for (int n = 0; n < 4; n++) {
                    int bt = n >> 1, sel = n & 1;
                    unsigned b0h = b_hi[bt][sel],     b1h = b_hi[bt][sel + 2];
                    unsigned b0l = b_lo[bt][sel],     b1l = b_lo[bt][sel + 2];
                    mma16816(acc[mt][n], a_hi[mt], b0h, b1h);
                    mma16816(acc[mt][n], a_hi[mt], b0l, b1l);
                    mma16816(acc[mt][n], a_lo[mt], b0h, b1h);
                }
        }
    };

    const int nkt = K / BK;
    load_stage(0, 0);
    asm volatile("cp.async.commit_group;\n");
    for (int kt = 0; kt < nkt; kt++) {
        if (kt + 1 < nkt) {
            load_stage((kt + 1) & 1, kt + 1);
            asm volatile("cp.async.commit_group;\n");
            asm volatile("cp.async.wait_group 1;\n");
        } else {
            asm volatile("cp.async.wait_group 0;\n");
        }
        __syncthreads();
        compute_stage(kt & 1);
        __syncthreads();
    }

    #pragma unroll
    for (int mt = 0; mt < 4; mt++) {
        int r0 = bi + wm * 64 + mt * 16 + (lane >> 2);
        #pragma unroll
        for (int n = 0; n < 4; n++) {
            int col = bj + wn * 32 + (n >> 1) * 16 + (n & 1) * 8 + 2 * (lane & 3);
            float2 v0 = {acc[mt][n][0], acc[mt][n][1]};
            float2 v1 = {acc[mt][n][2], acc[mt][n][3]};
            *(float2*)&C[(size_t)r0 * N + col] = v0;
            *(float2*)&C[(size_t)(r0 + 8) * N + col] = v1;
        }
    }
}

// ---------------- fp32 -> bf16 hi/lo conversion kernels ----------------------
__global__ void conv_split_kernel(const float* __restrict__ src,
                                  __nv_bfloat16* __restrict__ hi,
                                  __nv_bfloat16* __restrict__ lo, int n)
{
    int i = blockIdx.x * blockDim.x + threadIdx.x;
    if (i >= n) return;
    float v = src[i];
    __nv_bfloat16 h = __float2bfloat16(v);
    hi[i] = h;
    lo[i] = __float2bfloat16(v - __bfloat162float(h));
}

// W (K,N) row-major -> hi/lo (N,K) row-major (transposed)
__global__ void conv_split_trans_kernel(const float* __restrict__ W,
                                        __nv_bfloat16* __restrict__ hi,
                                        __nv_bfloat16* __restrict__ lo,
                                        int K, int N)
{
    __shared__ float t[32][33];
    int k0 = blockIdx.y * 32, n0 = blockIdx.x * 32;
    int tx = threadIdx.x, ty = threadIdx.y;   // (32, 8)
    #pragma unroll
    for (int r = ty; r < 32; r += 8)
        t[r][tx] = W[(size_t)(k0 + r) * N + n0 + tx];
    __syncthreads();
    #pragma unroll
    for (int r = ty; r < 32; r += 8) {
        float v = t[tx][r];                   // W[k0+tx][n0+r]
        __nv_bfloat16 h = __float2bfloat16(v);
        hi[(size_t)(n0 + r) * K + k0 + tx] = h;
        lo[(size_t)(n0 + r) * K + k0 + tx] = __float2bfloat16(v - __bfloat162float(h));
    }
}

// ---------------- generic tiled fp32 GEMM (scores / AV) ----------------------
template <int TRANSB, int CAUSAL, int CMODE>
__global__ __launch_bounds__(256)
void sgemm_kernel(const float* __restrict__ A, const float* __restrict__ Bm,
                  float* __restrict__ C,
                  int M, int N, int K, int lda, int ldb, int ldc,
                  long long sA, long long sB, long long sC, float alpha)
{
    int bz = blockIdx.z;
    A  += (long long)bz * sA;
    Bm += (long long)bz * sB;
    if (CMODE) C += (long long)(bz >> 4) * ((long long)Lq * HIDq) + (long long)(bz & 15) * Dq;
    else       C += (long long)bz * sC;

    int i0 = blockIdx.y * 64, j0 = blockIdx.x * 64;
    if (CAUSAL && j0 > i0 + 63) return;

    __shared__ float As[16][64];
    __shared__ float Bs[16][64];

    int tid = threadIdx.x;
    int tx = tid & 15, ty = tid >> 4;
    float acc[4][4] = {};

    for (int k0 = 0; k0 < K; k0 += 16) {
        #pragma unroll
        for (int t = tid; t < 1024; t += 256) {
            int m = t >> 4, kk = t & 15;
            As[kk][m] = A[(long long)(i0 + m) * lda + k0 + kk];
        }
        if (TRANSB) {
            #pragma unroll
            for (int t = tid; t < 1024; t += 256) {
                int n = t >> 4, kk = t & 15;
                Bs[kk][n] = Bm[(long long)(j0 + n) * ldb + k0 + kk];
            }
        } else {
            #pragma unroll
            for (int t = tid; t < 1024; t += 256) {
                int kk = t >> 6, n = t & 63;
                Bs[kk][n] = Bm[(long long)(k0 + kk) * ldb + j0 + n];
            }
        }
        __syncthreads();
        #pragma unroll
        for (int kk = 0; kk < 16; kk++) {
            float4 a4 = *(const float4*)&As[kk][ty * 4];
            float4 b4 = *(const float4*)&Bs[kk][tx * 4];
            float a[4] = {a4.x, a4.y, a4.z, a4.w};
            float b[4] = {b4.x, b4.y, b4.z, b4.w};
            #pragma unroll
            for (int x = 0; x < 4; x++)
                #pragma unroll
                for (int y = 0; y < 4; y++)
                    acc[x][y] += a[x] * b[y];
        }
        __syncthreads();
    }
    #pragma unroll
    for (int x = 0; x < 4; x++)
        #pragma unroll
        for (int y = 0; y < 4; y++)
            C[(long long)(i0 + ty * 4 + x) * ldc + j0 + tx * 4 + y] = alpha * acc[x][y];
}

// ---------------- qkv split + RoPE ------------------------------------------
__global__ void rope_split_kernel(const float* __restrict__ qkv,
                                  float* __restrict__ q, float* __restrict__ k,
                                  float* __restrict__ v)
{
    int idx = blockIdx.x * blockDim.x + threadIdx.x;
    if (idx >= Bq * Hq * Lq * Dq) return;
    int d = idx & 63;
    int l = (idx >> 6) & 1023;
    int h = (idx >> 16) & 15;
    int b = idx >> 20;

    long long base = ((long long)(b * Lq + l) * 3) * (Hq * Dq) + h * Dq;
    float qa = qkv[base + d];
    float ka = qkv[base + Hq * Dq + d];
    float vv = qkv[base + 2 * Hq * Dq + d];
    int dp = (d < 32) ? d + 32 : d - 32;
    float qb = qkv[base + dp];
    float kb = qkv[base + Hq * Dq + dp];

    int fi = (d < 32) ? d : d - 32;
    float ang = (float)l * powf(10000.0f, -(float)fi / 32.0f);
    float c = cosf(ang), s = sinf(ang);
    float sgn = (d < 32) ? -1.0f : 1.0f;

    long long o = ((long long)(b * Hq + h) * Lq + l) * Dq + d;
    q[o] = qa * c + sgn * qb * s;
    k[o] = ka * c + sgn * kb * s;
    v[o] = vv;
}

// ---------------- DAPE tables: kc[o][dist], ktab[h][dist] --------------------
__global__ void dape_pre_kernel(const float* __restrict__ w1, const float* __restrict__ b1,
                                const float* __restrict__ log_p, const float* __restrict__ log_a,
                                float* __restrict__ kc_t, float* __restrict__ ktab_t)
{
    int dist = blockIdx.x;
    int t = threadIdx.x;    // 32
    __shared__ float kv[16];
    if (t < 16) {
        float p = log1pf(expf(log_p[t]));
        float a = log1pf(expf(log_a[t]));
        float kvv = -p * log1pf(a * (float)dist);
        kv[t] = kvv;
        ktab_t[t * 1024 + dist] = kvv;
    }
    __syncthreads();
    float acc = b1[t];
    #pragma unroll
    for (int h = 0; h < 16; h++) acc += kv[h] * w1[(16 + h) * 32 + t];
    kc_t[t * 1024 + dist] = acc;
}

// ---------------- fused DAPE MLP + kerple + causal softmax -------------------
// One block per (b,i), 1024 threads, 1 j per thread.
__global__ __launch_bounds__(1024, 1)
void dape_softmax_kernel(float* __restrict__ scores,
                         const float* __restrict__ w1, const float* __restrict__ w2,
                         const float* __restrict__ b2,
                         const float* __restrict__ kc_t, const float* __restrict__ ktab_t)
{
    __shared__ float s_w1[512];   // first 16 rows of w1: [h*32+o]
    __shared__ float s_w2[512];   // [o*16+h]
    __shared__ float s_b2[16];
    __shared__ float s_red[16 * 32];
    __shared__ float s_bc[16];

    int tid = threadIdx.x;
    int i = blockIdx.x & (Lq - 1);
    int b = blockIdx.x >> 10;

    if (tid < 512) { s_w1[tid] = w1[tid]; s_w2[tid] = w2[tid]; }
    if (tid < 16)  s_b2[tid] = b2[tid];
    __syncthreads();

    long long base0 = (long long)b * (Hq * Lq * Lq) + (long long)i * Lq;
    int j = tid;
    float out[16];

    if (j <= i) {
        int dist = i - j;
        float s[16];
        #pragma unroll
        for (int h = 0; h < 16; h++)
            s[h] = scores[base0 + (long long)h * (Lq * Lq) + j];
        #pragma unroll
        for (int h = 0; h < 16; h++)
            out[h] = s[h] + ktab_t[h * 1024 + dist] + s_b2[h];
        #pragma unroll 8
        for (int o = 0; o < 32; o++) {
            float acc = kc_t[o * 1024 + dist];
            #pragma unroll
            for (int h = 0; h < 16; h++) acc += s[h] * s_w1[h * 32 + o];
            float g = 0.5f * acc * (1.0f + erff(acc * 0.70710678118654752f));
            #pragma unroll
            for (int h = 0; h < 16; h++) out[h] += g * s_w2[o * 16 + h];
        }
    } else {
        #pragma unroll
        for (int h = 0; h < 16; h++) out[h] = -INFINITY;
    }

    int warp = tid >> 5, ln = tid & 31;

    // per-head max
    #pragma unroll
    for (int h = 0; h < 16; h++) {
        float v = out[h];
        #pragma unroll
        for (int off = 16; off > 0; off >>= 1)
            v = fmaxf(v, __shfl_xor_sync(0xffffffffu, v, off));
        if (ln == 0) s_red[h * 32 + warp] = v;
    }
    __syncthreads();
    if (tid < 16) {
        float v = s_red[tid * 32];
        #pragma unroll
        for (int w = 1; w < 32; w++) v = fmaxf(v, s_red[tid * 32 + w]);
        s_bc[tid] = v;
    }
    __syncthreads();
    float mx[16];
    #pragma unroll
    for (int h = 0; h < 16; h++) mx[h] = s_bc[h];
    __syncthreads();

    // exp + per-head sum
    #pragma unroll
    for (int h = 0; h < 16; h++) out[h] = expf(out[h] - mx[h]);   // exp(-inf)=0
    #pragma unroll
    for (int h = 0; h < 16; h++) {
        float v = out[h];
        #pragma unroll
        for (int off = 16; off > 0; off >>= 1)
            v += __shfl_xor_sync(0xffffffffu, v, off);
        if (ln == 0) s_red[h * 32 + warp] = v;
    }
    __syncthreads();
    if (tid < 16) {
        float v = 0.0f;
        #pragma unroll
        for (int w = 0; w < 32; w++) v += s_red[tid * 32 + w];
        s_bc[tid] = 1.0f / v;
    }
    __syncthreads();

    #pragma unroll
    for (int h = 0; h < 16; h++)
        scores[base0 + (long long)h * (Lq * Lq) + j] = out[h] * s_bc[h];
}

// ---------------- launch ----------------------------------------------------
extern "C" void kernel_launch(void* const* d_in, const int* in_sizes, int n_in,
                              void* d_out, int out_size)
{
    const float* x     = (const float*)d_in[0];
    const float* w_qkv = (const float*)d_in[1];
    const float* w_o   = (const float*)d_in[2];
    const float* log_p = (const float*)d_in[3];
    const float* log_a = (const float*)d_in[4];
    const float* w1    = (const float*)d_in[5];
    const float* b1    = (const float*)d_in[6];
    const float* w2    = (const float*)d_in[7];
    const float* b2    = (const float*)d_in[8];
    float* out = (float*)d_out;
    (void)in_sizes; (void)n_in; (void)out_size;

    float *qkv, *q, *k, *v, *sc, *attn, *kc, *ktab;
    __nv_bfloat16 *xhi, *xlo, *wqT_hi, *wqT_lo, *ahi, *alo, *woT_hi, *woT_lo;
    cudaGetSymbolAddress((void**)&qkv,  g_qkv);
    cudaGetSymbolAddress((void**)&q,    g_q);
    cudaGetSymbolAddress((void**)&k,    g_k);
    cudaGetSymbolAddress((void**)&v,    g_v);
    cudaGetSymbolAddress((void**)&sc,   g_sc);
    cudaGetSymbolAddress((void**)&attn, g_attn);
    cudaGetSymbolAddress((void**)&kc,   g_kc);
    cudaGetSymbolAddress((void**)&ktab, g_ktab);
    cudaGetSymbolAddress((void**)&xhi,    g_xhi);
    cudaGetSymbolAddress((void**)&xlo,    g_xlo);
    cudaGetSymbolAddress((void**)&wqT_hi, g_wqkvT_hi);
    cudaGetSymbolAddress((void**)&wqT_lo, g_wqkvT_lo);
    cudaGetSymbolAddress((void**)&ahi,    g_ahi);
    cudaGetSymbolAddress((void**)&alo,    g_alo);
    cudaGetSymbolAddress((void**)&woT_hi, g_woT_hi);
    cudaGetSymbolAddress((void**)&woT_lo, g_woT_lo);

    static int smem_set = 0;
    if (!smem_set) {
        cudaFuncSetAttribute(hgemm_split_kernel,
                             cudaFuncAttributeMaxDynamicSharedMemorySize, 65536);
        smem_set = 1;
    }

    const int M = Bq * Lq;           // 2048
    const int TH = 3 * Hq * Dq;      // 3072

    // 0) DAPE tables (independent)
    dape_pre_kernel<<<1024, 32>>>(w1, b1, log_p, log_a, kc, ktab);

    // 1) split-precision conversions for qkv GEMM
    conv_split_kernel<<<(M * HIDq) / 256, 256>>>(x, xhi, xlo, M * HIDq);
    conv_split_trans_kernel<<<dim3(TH / 32, HIDq / 32), dim3(32, 8)>>>(
        w_qkv, wqT_hi, wqT_lo, HIDq, TH);

    // 2) qkv = x @ w_qkv via bf16 split tensor cores
    hgemm_split_kernel<<<dim3(TH / BN, M / BM), 256, 65536>>>(
        xhi, xlo, wqT_hi, wqT_lo, qkv, M, TH, HIDq);

    // 3) split + RoPE
    rope_split_kernel<<<(Bq * Hq * Lq * Dq) / 256, 256>>>(qkv, q, k, v);

    // 4) scores = (q @ k^T) / sqrt(D), batched, causal block skip (fp32)
    sgemm_kernel<1, 1, 0><<<dim3(Lq / 64, Lq / 64, Bq * Hq), 256>>>(
        q, k, sc, Lq, Lq, Dq, Dq, Dq, Lq,
        (long long)Lq * Dq, (long long)Lq * Dq, (long long)Lq * Lq, 0.125f);

    // 5) fused kerple + DAPE MLP + causal softmax
    dape_softmax_kernel<<<Bq * Lq, 1024>>>(sc, w1, w2, b2, kc, ktab);

    // 6) attn(B,L,H*D) = weights @ v (fp32, CMODE transposed write)
    sgemm_kernel<0, 0, 1><<<dim3(1, Lq / 64, Bq * Hq), 256>>>(
        sc, v, attn, Lq, Dq, Lq, Lq, Dq, HIDq,
        (long long)Lq * Lq, (long long)Lq * Dq, 0, 1.0f);

    // 7) out = attn @ w_o via bf16 split tensor cores
    conv_split_kernel<<<(M * HIDq) / 256, 256>>>(attn, ahi, alo, M * HIDq);
    conv_split_trans_kernel<<<dim3(HIDq / 32, HIDq / 32), dim3(32, 8)>>>(
        w_o, woT_hi, woT_lo, HIDq, HIDq);
    hgemm_split_kernel<<<dim3(HIDq / BN, M / BM), 256, 65536>>>(
        ahi, alo, woT_hi, woT_lo, out, M, HIDq, HIDq);
}

// round 5
// speedup vs baseline: 2.2227x; 1.3880x over previous
#include <cuda_runtime.h>
#include <cuda_bf16.h>
#include <math.h>

#define Bq   2
#define Lq   1024
#define Hq   16
#define Dq   64
#define HIDq 1024

typedef __nv_bfloat16 bf16;

// ---------------- scratch (static device globals; no runtime alloc) ----------
__device__ float g_qkv[Bq * Lq * 3 * Hq * Dq];                  // (B,L,3,H,D)
__device__ float g_sc[(long long)Bq * Hq * Lq * Lq];            // (B,H,L,L) fp32 scores

__device__ bf16 g_qhi[Bq * Hq * Lq * Dq], g_qlo[Bq * Hq * Lq * Dq];   // (B,H,L,D)
__device__ bf16 g_khi[Bq * Hq * Lq * Dq], g_klo[Bq * Hq * Lq * Dq];
__device__ bf16 g_vThi[Bq * Hq * Dq * Lq], g_vTlo[Bq * Hq * Dq * Lq]; // (B,H,D,L)
__device__ bf16 g_whi[(long long)Bq * Hq * Lq * Lq];                  // weights hi
__device__ bf16 g_wlo[(long long)Bq * Hq * Lq * Lq];                  // weights lo

__device__ bf16 g_xhi[2048 * 1024], g_xlo[2048 * 1024];
__device__ bf16 g_wqkvT_hi[3072 * 1024], g_wqkvT_lo[3072 * 1024];
__device__ bf16 g_attnhi[2048 * 1024], g_attnlo[2048 * 1024];   // (B,L,H*D)
__device__ bf16 g_woT_hi[1024 * 1024], g_woT_lo[1024 * 1024];

// DAPE precomputed tables
__device__ float g_kc[32 * 1024];     // [o][dist]
__device__ float g_ktab[16 * 1024];   // [h][dist]

// ======================= split-bf16 tensor-core GEMM ========================
#define BM 128
#define BK 32
#define NSTG 3

__device__ __forceinline__ void ldm_x4(unsigned r[4], unsigned addr) {
    asm volatile("ldmatrix.sync.aligned.m8n8.x4.shared.b16 {%0,%1,%2,%3}, [%4];"
        : "=r"(r[0]), "=r"(r[1]), "=r"(r[2]), "=r"(r[3]) : "r"(addr));
}
__device__ __forceinline__ void mma16816(float c[4], const unsigned a[4],
                                         unsigned b0, unsigned b1) {
    asm volatile("mma.sync.aligned.m16n8k16.row.col.f32.bf16.bf16.f32 "
        "{%0,%1,%2,%3},{%4,%5,%6,%7},{%8,%9},{%0,%1,%2,%3};"
        : "+f"(c[0]), "+f"(c[1]), "+f"(c[2]), "+f"(c[3])
        : "r"(a[0]), "r"(a[1]), "r"(a[2]), "r"(a[3]), "r"(b0), "r"(b1));
}
__device__ __forceinline__ void cp16(unsigned saddr, const void* g) {
    asm volatile("cp.async.cg.shared.global [%0], [%1], 16;\n" :: "r"(saddr), "l"(g));
}

// C = alpha * A(M,K) x B(N,K)^T, split precision hh+hl+lh.
// CJ: skip output tiles with j0 > i0+BM-1 (causal scores)
// CK: clamp K to i0+BM (causal AV)
// OUT: 0 = fp32 C (alpha, batch stride sC); 1 = bf16 hi/lo pair, attn layout
template <int BN_, int CJ, int CK, int OUT>
__global__ __launch_bounds__(256)
void hgemm_kernel(const bf16* __restrict__ Ahi, const bf16* __restrict__ Alo,
                  const bf16* __restrict__ Bhi, const bf16* __restrict__ Blo,
                  float* __restrict__ Cf, bf16* __restrict__ Chi, bf16* __restrict__ Clo,
                  int M, int N, int K, int lda, int ldb, int ldc,
                  long long sA, long long sB, long long sC, float alpha)
{
    constexpr int WCOL = BN_ / 4;          // 32 or 16
    constexpr int NT = WCOL / 16;          // 2 or 1
    constexpr unsigned BOFF = 16384u;                  // B_hi smem offset
    constexpr unsigned BLO  = 16384u + BN_ * 64u;      // B_lo
    constexpr unsigned STG  = 16384u + BN_ * 128u;     // stage bytes

    const int bz = blockIdx.z;
    Ahi += (long long)bz * sA;  Alo += (long long)bz * sA;
    Bhi += (long long)bz * sB;  Blo += (long long)bz * sB;

    const int bi = blockIdx.y * BM, bj = blockIdx.x * BN_;
    if (CJ && bj > bi + BM - 1) return;

    extern __shared__ bf16 smem[];
    const unsigned sgen = (unsigned)__cvta_generic_to_shared(smem);
    const int tid = threadIdx.x;
    const int wid = tid >> 5, lane = tid & 31;
    const int wm = wid >> 2, wn = wid & 3;

    float acc[4][2 * NT][4];
    #pragma unroll
    for (int a = 0; a < 4; a++)
        #pragma unroll
        for (int b = 0; b < 2 * NT; b++)
            #pragma unroll
            for (int c = 0; c < 4; c++) acc[a][b][c] = 0.f;

    const int kmax = CK ? (bi + BM < K ? bi + BM : K) : K;
    const int nkt = kmax / BK;

    auto load_stage = [&](int stage, int kt) {
        int k0 = kt * BK;
        unsigned sb = sgen + stage * STG;
        #pragma unroll
        for (int rep = 0; rep < 2; rep++) {
            int c = tid + rep * 256;
            int row = c >> 2, kc = c & 3;
            unsigned swc = (unsigned)(kc ^ ((row >> 1) & 3));
            unsigned so = sb + (unsigned)row * 64u + swc * 16u;
            cp16(so,         Ahi + (size_t)(bi + row) * lda + k0 + kc * 8);
            cp16(so + 8192u, Alo + (size_t)(bi + row) * lda + k0 + kc * 8);
        }
        #pragma unroll
        for (int rep = 0; rep < BN_ / 64; rep++) {
            int c = tid + rep * 256;
            int row = c >> 2, kc = c & 3;
            unsigned swc = (unsigned)(kc ^ ((row >> 1) & 3));
            unsigned so = sb + (unsigned)row * 64u + swc * 16u;
            cp16(so + BOFF, Bhi + (size_t)(bj + row) * ldb + k0 + kc * 8);
            cp16(so + BLO,  Blo + (size_t)(bj + row) * ldb + k0 + kc * 8);
        }
    };

    auto compute_stage = [&](int stage) {
        unsigned sb = sgen + stage * STG;
        #pragma unroll
        for (int ks = 0; ks < 2; ks++) {
            int r = lane & 15;
            int cc = ks * 2 + (lane >> 4);
            unsigned a_hi[4][4], a_lo[4][4];
            #pragma unroll
            for (int mt = 0; mt < 4; mt++) {
                int row = wm * 64 + mt * 16 + r;
                unsigned swc = (unsigned)(cc ^ ((row >> 1) & 3));
                unsigned addr = sb + (unsigned)row * 64u + swc * 16u;
                ldm_x4(a_hi[mt], addr);
                ldm_x4(a_lo[mt], addr + 8192u);
            }
            unsigned b_hi[NT][4], b_lo[NT][4];
            #pragma unroll
            for (int bt = 0; bt < NT; bt++) {
                int row = wn * WCOL + bt * 16 + r;
                unsigned swc = (unsigned)(cc ^ ((row >> 1) & 3));
                unsigned addr = sb + BOFF + (unsigned)row * 64u + swc * 16u;
                ldm_x4(b_hi[bt], addr);
                ldm_x4(b_lo[bt], addr + (BN_ * 64u));
            }
            #pragma unroll
            for (int mt = 0; mt < 4; mt++)
                #pragma unroll
                for (int n = 0; n < 2 * NT; n++) {
                    int bt = n >> 1, sel = n & 1;
                    unsigned b0h = b_hi[bt][sel], b1h = b_hi[bt][sel + 2];
                    unsigned b0l = b_lo[bt][sel], b1l = b_lo[bt][sel + 2];
                    mma16816(acc[mt][n], a_hi[mt], b0h, b1h);
                    mma16816(acc[mt][n], a_hi[mt], b0l, b1l);
                    mma16816(acc[mt][n], a_lo[mt], b0h, b1h);
                }
        }
    };

    // ---- 3-stage pipeline, one barrier per iteration ----
    #pragma unroll
    for (int s = 0; s < NSTG - 1; s++) {
        if (s < nkt) load_stage(s, s);
        asm volatile("cp.async.commit_group;\n");
    }
    for (int kt = 0; kt < nkt; kt++) {
        asm volatile("cp.async.wait_group %0;\n" :: "n"(NSTG - 2));
        __syncthreads();
        int kn = kt + NSTG - 1;
        if (kn < nkt) load_stage(kn % NSTG, kn);
        asm volatile("cp.async.commit_group;\n");
        compute_stage(kt % NSTG);
    }

    // ---- epilogue ----
    #pragma unroll
    for (int mt = 0; mt < 4; mt++) {
        int r0 = bi + wm * 64 + mt * 16 + (lane >> 2);
        #pragma unroll
        for (int n = 0; n < 2 * NT; n++) {
            int col = bj + wn * WCOL + (n >> 1) * 16 + (n & 1) * 8 + 2 * (lane & 3);
            if (OUT == 0) {
                float* C = Cf + (long long)bz * sC;
                float2 v0 = {alpha * acc[mt][n][0], alpha * acc[mt][n][1]};
                float2 v1 = {alpha * acc[mt][n][2], alpha * acc[mt][n][3]};
                *(float2*)&C[(size_t)r0 * ldc + col] = v0;
                *(float2*)&C[(size_t)(r0 + 8) * ldc + col] = v1;
            } else {
                long long base = (long long)(bz >> 4) * ((long long)Lq * HIDq)
                               + (long long)(bz & 15) * Dq;
                #pragma unroll
                for (int rr = 0; rr < 2; rr++) {
                    float va = acc[mt][n][rr * 2], vb = acc[mt][n][rr * 2 + 1];
                    bf16 ha = __float2bfloat16(va), hb = __float2bfloat16(vb);
                    bf16 la = __float2bfloat16(va - __bfloat162float(ha));
                    bf16 lb = __float2bfloat16(vb - __bfloat162float(hb));
                    size_t off = base + (size_t)(r0 + rr * 8) * ldc + col;
                    *(__nv_bfloat162*)&Chi[off] = __nv_bfloat162(ha, hb);
                    *(__nv_bfloat162*)&Clo[off] = __nv_bfloat162(la, lb);
                }
            }
        }
    }
}

// ---------------- fp32 -> bf16 hi/lo conversion kernels ----------------------
__global__ void conv_split_kernel(const float* __restrict__ src,
                                  bf16* __restrict__ hi, bf16* __restrict__ lo, int n)
{
    int i = blockIdx.x * blockDim.x + threadIdx.x;
    if (i >= n) return;
    float v = src[i];
    bf16 h = __float2bfloat16(v);
    hi[i] = h;
    lo[i] = __float2bfloat16(v - __bfloat162float(h));
}

__global__ void conv_split_trans_kernel(const float* __restrict__ W,
                                        bf16* __restrict__ hi, bf16* __restrict__ lo,
                                        int K, int N)
{
    __shared__ float t[32][33];
    int k0 = blockIdx.y * 32, n0 = blockIdx.x * 32;
    int tx = threadIdx.x, ty = threadIdx.y;
    #pragma unroll
    for (int r = ty; r < 32; r += 8)
        t[r][tx] = W[(size_t)(k0 + r) * N + n0 + tx];
    __syncthreads();
    #pragma unroll
    for (int r = ty; r < 32; r += 8) {
        float v = t[tx][r];
        bf16 h = __float2bfloat16(v);
        hi[(size_t)(n0 + r) * K + k0 + tx] = h;
        lo[(size_t)(n0 + r) * K + k0 + tx] = __float2bfloat16(v - __bfloat162float(h));
    }
}

// ---------------- qkv split + RoPE -> bf16 hi/lo (q,k) + transposed v -------
// One block per (b, h, 32-row l-tile). 256 threads.
__global__ __launch_bounds__(256)
void rope_split_kernel(const float* __restrict__ qkv,
                       bf16* __restrict__ qhi, bf16* __restrict__ qlo,
                       bf16* __restrict__ khi, bf16* __restrict__ klo,
                       bf16* __restrict__ vThi, bf16* __restrict__ vTlo)
{
    __shared__ float sv[32][65];
    int bid = blockIdx.x;
    int l0 = (bid & 31) * 32;
    int h = (bid >> 5) & 15;
    int b = bid >> 9;
    int tid = threadIdx.x;

    #pragma unroll
    for (int e = 0; e < 8; e++) {
        int idx = tid + e * 256;
        int d = idx & 63, lr = idx >> 6;
        int l = l0 + lr;
        long long base = ((long long)(b * Lq + l) * 3) * (Hq * Dq) + h * Dq;
        float qa = qkv[base + d];
        float ka = qkv[base + Hq * Dq + d];
        float vv = qkv[base + 2 * Hq * Dq + d];
        int dp = (d < 32) ? d + 32 : d - 32;
        float qb = qkv[base + dp];
        float kb = qkv[base + Hq * Dq + dp];

        int fi = (d < 32) ? d : d - 32;
        float ang = (float)l * powf(10000.0f, -(float)fi / 32.0f);
        float c = cosf(ang), s = sinf(ang);
        float sgn = (d < 32) ? -1.0f : 1.0f;

        float qv = qa * c + sgn * qb * s;
        float kv = ka * c + sgn * kb * s;

        long long o = ((long long)(b * Hq + h) * Lq + l) * Dq + d;
        bf16 qh = __float2bfloat16(qv), kh = __float2bfloat16(kv);
        qhi[o] = qh; qlo[o] = __float2bfloat16(qv - __bfloat162float(qh));
        khi[o] = kh; klo[o] = __float2bfloat16(kv - __bfloat162float(kh));
        sv[lr][d] = vv;
    }
    __syncthreads();
    #pragma unroll
    for (int e = 0; e < 8; e++) {
        int idx = tid + e * 256;
        int lr = idx & 31, d = idx >> 5;
        float vv = sv[lr][d];
        bf16 vh = __float2bfloat16(vv);
        long long o = ((long long)(b * Hq + h) * Dq + d) * Lq + l0 + lr;
        vThi[o] = vh;
        vTlo[o] = __float2bfloat16(vv - __bfloat162float(vh));
    }
}

// ---------------- DAPE tables: kc[o][dist], ktab[h][dist] --------------------
__global__ void dape_pre_kernel(const float* __restrict__ w1, const float* __restrict__ b1,
                                const float* __restrict__ log_p, const float* __restrict__ log_a,
                                float* __restrict__ kc_t, float* __restrict__ ktab_t)
{
    int dist = blockIdx.x;
    int t = threadIdx.x;    // 32
    __shared__ float kv[16];
    if (t < 16) {
        float p = log1pf(expf(log_p[t]));
        float a = log1pf(expf(log_a[t]));
        float kvv = -p * log1pf(a * (float)dist);
        kv[t] = kvv;
        ktab_t[t * 1024 + dist] = kvv;
    }
    __syncthreads();
    float acc = b1[t];
    #pragma unroll
    for (int h = 0; h < 16; h++) acc += kv[h] * w1[(16 + h) * 32 + t];
    kc_t[t * 1024 + dist] = acc;
}

// ---------------- fused DAPE MLP + kerple + causal softmax -------------------
// One block per (b,i), 1024 threads, 1 j per thread. Emits bf16 hi/lo weights.
__global__ __launch_bounds__(1024, 1)
void dape_softmax_kernel(const float* __restrict__ scores,
                         bf16* __restrict__ whi, bf16* __restrict__ wlo,
                         const float* __restrict__ w1, const float* __restrict__ w2,
                         const float* __restrict__ b2,
                         const float* __restrict__ kc_t, const float* __restrict__ ktab_t)
{
    __shared__ float s_w1[512];
    __shared__ float s_w2[512];
    __shared__ float s_b2[16];
    __shared__ float s_red[16 * 32];
    __shared__ float s_bc[16];

    int tid = threadIdx.x;
    int i = blockIdx.x & (Lq - 1);
    int b = blockIdx.x >> 10;

    if (tid < 512) { s_w1[tid] = w1[tid]; s_w2[tid] = w2[tid]; }
    if (tid < 16)  s_b2[tid] = b2[tid];
    __syncthreads();

    long long base0 = (long long)b * (Hq * Lq * Lq) + (long long)i * Lq;
    int j = tid;
    float out[16];

    if (j <= i) {
        int dist = i - j;
        float s[16];
        #pragma unroll
        for (int h = 0; h < 16; h++)
            s[h] = scores[base0 + (long long)h * (Lq * Lq) + j];
        #pragma unroll
        for (int h = 0; h < 16; h++)
            out[h] = s[h] + ktab_t[h * 1024 + dist] + s_b2[h];
        #pragma unroll 8
        for (int o = 0; o < 32; o++) {
            float acc = kc_t[o * 1024 + dist];
            #pragma unroll
            for (int h = 0; h < 16; h++) acc += s[h] * s_w1[h * 32 + o];
            float g = 0.5f * acc * (1.0f + erff(acc * 0.70710678118654752f));
            #pragma unroll
            for (int h = 0; h < 16; h++) out[h] += g * s_w2[o * 16 + h];
        }
    } else {
        #pragma unroll
        for (int h = 0; h < 16; h++) out[h] = -INFINITY;
    }

    int warp = tid >> 5, ln = tid & 31;

    #pragma unroll
    for (int h = 0; h < 16; h++) {
        float v = out[h];
        #pragma unroll
        for (int off = 16; off > 0; off >>= 1)
            v = fmaxf(v, __shfl_xor_sync(0xffffffffu, v, off));
        if (ln == 0) s_red[h * 32 + warp] = v;
    }
    __syncthreads();
    if (tid < 16) {
        float v = s_red[tid * 32];
        #pragma unroll
        for (int w = 1; w < 32; w++) v = fmaxf(v, s_red[tid * 32 + w]);
        s_bc[tid] = v;
    }
    __syncthreads();
    float mx[16];
    #pragma unroll
    for (int h = 0; h < 16; h++) mx[h] = s_bc[h];
    __syncthreads();

    #pragma unroll
    for (int h = 0; h < 16; h++) out[h] = expf(out[h] - mx[h]);
    #pragma unroll
    for (int h = 0; h < 16; h++) {
        float v = out[h];
        #pragma unroll
        for (int off = 16; off > 0; off >>= 1)
            v += __shfl_xor_sync(0xffffffffu, v, off);
        if (ln == 0) s_red[h * 32 + warp] = v;
    }
    __syncthreads();
    if (tid < 16) {
        float v = 0.0f;
        #pragma unroll
        for (int w = 0; w < 32; w++) v += s_red[tid * 32 + w];
        s_bc[tid] = 1.0f / v;
    }
    __syncthreads();

    #pragma unroll
    for (int h = 0; h < 16; h++) {
        float w = out[h] * s_bc[h];
        bf16 hv = __float2bfloat16(w);
        long long off = base0 + (long long)h * (Lq * Lq) + j;
        whi[off] = hv;
        wlo[off] = __float2bfloat16(w - __bfloat162float(hv));
    }
}

// ---------------- launch ----------------------------------------------------
extern "C" void kernel_launch(void* const* d_in, const int* in_sizes, int n_in,
                              void* d_out, int out_size)
{
    const float* x     = (const float*)d_in[0];
    const float* w_qkv = (const float*)d_in[1];
    const float* w_o   = (const float*)d_in[2];
    const float* log_p = (const float*)d_in[3];
    const float* log_a = (const float*)d_in[4];
    const float* w1    = (const float*)d_in[5];
    const float* b1    = (const float*)d_in[6];
    const float* w2    = (const float*)d_in[7];
    const float* b2    = (const float*)d_in[8];
    float* out = (float*)d_out;
    (void)in_sizes; (void)n_in; (void)out_size;

    float *qkv, *sc, *kc, *ktab;
    bf16 *qhi, *qlo, *khi, *klo, *vThi, *vTlo, *whi, *wlo;
    bf16 *xhi, *xlo, *wqT_hi, *wqT_lo, *attnhi, *attnlo, *woT_hi, *woT_lo;
    cudaGetSymbolAddress((void**)&qkv,  g_qkv);
    cudaGetSymbolAddress((void**)&sc,   g_sc);
    cudaGetSymbolAddress((void**)&kc,   g_kc);
    cudaGetSymbolAddress((void**)&ktab, g_ktab);
    cudaGetSymbolAddress((void**)&qhi,  g_qhi);
    cudaGetSymbolAddress((void**)&qlo,  g_qlo);
    cudaGetSymbolAddress((void**)&khi,  g_khi);
    cudaGetSymbolAddress((void**)&klo,  g_klo);
    cudaGetSymbolAddress((void**)&vThi, g_vThi);
    cudaGetSymbolAddress((void**)&vTlo, g_vTlo);
    cudaGetSymbolAddress((void**)&whi,  g_whi);
    cudaGetSymbolAddress((void**)&wlo,  g_wlo);
    cudaGetSymbolAddress((void**)&xhi,    g_xhi);
    cudaGetSymbolAddress((void**)&xlo,    g_xlo);
    cudaGetSymbolAddress((void**)&wqT_hi, g_wqkvT_hi);
    cudaGetSymbolAddress((void**)&wqT_lo, g_wqkvT_lo);
    cudaGetSymbolAddress((void**)&attnhi, g_attnhi);
    cudaGetSymbolAddress((void**)&attnlo, g_attnlo);
    cudaGetSymbolAddress((void**)&woT_hi, g_woT_hi);
    cudaGetSymbolAddress((void**)&woT_lo, g_woT_lo);

    static int smem_set = 0;
    if (!smem_set) {
        cudaFuncSetAttribute(hgemm_kernel<128, 0, 0, 0>,
                             cudaFuncAttributeMaxDynamicSharedMemorySize, 3 * 32768);
        cudaFuncSetAttribute(hgemm_kernel<128, 1, 0, 0>,
                             cudaFuncAttributeMaxDynamicSharedMemorySize, 3 * 32768);
        cudaFuncSetAttribute(hgemm_kernel<64, 0, 1, 1>,
                             cudaFuncAttributeMaxDynamicSharedMemorySize, 3 * 24576);
        smem_set = 1;
    }

    const int M = Bq * Lq;           // 2048
    const int TH = 3 * Hq * Dq;      // 3072

    // 0) DAPE tables
    dape_pre_kernel<<<1024, 32>>>(w1, b1, log_p, log_a, kc, ktab);

    // 1) conversions for qkv GEMM
    conv_split_kernel<<<(M * HIDq) / 256, 256>>>(x, xhi, xlo, M * HIDq);
    conv_split_trans_kernel<<<dim3(TH / 32, HIDq / 32), dim3(32, 8)>>>(
        w_qkv, wqT_hi, wqT_lo, HIDq, TH);

    // 2) qkv = x @ w_qkv (tensor cores)
    hgemm_kernel<128, 0, 0, 0><<<dim3(TH / 128, M / 128), 256, 3 * 32768>>>(
        xhi, xlo, wqT_hi, wqT_lo, qkv, nullptr, nullptr,
        M, TH, HIDq, HIDq, HIDq, TH, 0, 0, 0, 1.0f);

    // 3) split + RoPE -> bf16 hi/lo q,k + transposed v
    rope_split_kernel<<<Bq * Hq * (Lq / 32), 256>>>(qkv, qhi, qlo, khi, klo, vThi, vTlo);

    // 4) scores = (q @ k^T)/8, batched 32, causal tile skip (tensor cores)
    hgemm_kernel<128, 1, 0, 0><<<dim3(Lq / 128, Lq / 128, Bq * Hq), 256, 3 * 32768>>>(
        qhi, qlo, khi, klo, sc, nullptr, nullptr,
        Lq, Lq, Dq, Dq, Dq, Lq,
        (long long)Lq * Dq, (long long)Lq * Dq, (long long)Lq * Lq, 0.125f);

    // 5) fused kerple + DAPE MLP + causal softmax -> bf16 hi/lo weights
    dape_softmax_kernel<<<Bq * Lq, 1024>>>(sc, whi, wlo, w1, w2, b2, kc, ktab);

    // 6) attn = weights @ v (tensor cores, causal-K, bf16 hi/lo out in (B,L,H*D))
    hgemm_kernel<64, 0, 1, 1><<<dim3(1, Lq / 128, Bq * Hq), 256, 3 * 24576>>>(
        whi, wlo, vThi, vTlo, nullptr, attnhi, attnlo,
        Lq, Dq, Lq, Lq, Lq, HIDq,
        (long long)Lq * Lq, (long long)Dq * Lq, 0, 1.0f);

    // 7) out = attn @ w_o (tensor cores)
    conv_split_trans_kernel<<<dim3(HIDq / 32, HIDq / 32), dim3(32, 8)>>>(
        w_o, woT_hi, woT_lo, HIDq, HIDq);
    hgemm_kernel<128, 0, 0, 0><<<dim3(HIDq / 128, M / 128), 256, 3 * 32768>>>(
        attnhi, attnlo, woT_hi, woT_lo, out, nullptr, nullptr,
        M, HIDq, HIDq, HIDq, HIDq, HIDq, 0, 0, 0, 1.0f);
}

// round 6
// speedup vs baseline: 2.9876x; 1.3441x over previous
#include <cuda_runtime.h>
#include <cuda_bf16.h>
#include <math.h>

#define Bq   2
#define Lq   1024
#define Hq   16
#define Dq   64
#define HIDq 1024

typedef __nv_bfloat16 bf16;
typedef unsigned long long ull;

// ---------------- scratch (static device globals; no runtime alloc) ----------
__device__ float g_qkv[Bq * Lq * 3 * Hq * Dq];                  // (B,L,3,H,D)
__device__ float g_sc[(long long)Bq * Hq * Lq * Lq];            // (B,H,L,L) fp32 scores

__device__ bf16 g_qhi[Bq * Hq * Lq * Dq], g_qlo[Bq * Hq * Lq * Dq];   // (B,H,L,D)
__device__ bf16 g_khi[Bq * Hq * Lq * Dq], g_klo[Bq * Hq * Lq * Dq];
__device__ bf16 g_vThi[Bq * Hq * Dq * Lq], g_vTlo[Bq * Hq * Dq * Lq]; // (B,H,D,L)
__device__ bf16 g_whi[(long long)Bq * Hq * Lq * Lq];                  // weights hi
__device__ bf16 g_wlo[(long long)Bq * Hq * Lq * Lq];                  // weights lo

__device__ bf16 g_xhi[2048 * 1024], g_xlo[2048 * 1024];
__device__ bf16 g_wqkvT_hi[3072 * 1024], g_wqkvT_lo[3072 * 1024];
__device__ bf16 g_attnhi[2048 * 1024], g_attnlo[2048 * 1024];   // (B,L,H*D)
__device__ bf16 g_woT_hi[1024 * 1024], g_woT_lo[1024 * 1024];

// DAPE precomputed tables
__device__ float g_kc[32 * 1024];     // [o][dist]
__device__ float g_ktab[16 * 1024];   // [h][dist]

// ---------------- f32x2 packed helpers ---------------------------------------
__device__ __forceinline__ ull pk2(float lo, float hi) {
    ull r; asm("mov.b64 %0,{%1,%2};" : "=l"(r) : "f"(lo), "f"(hi)); return r;
}
__device__ __forceinline__ void upk2(ull v, float& lo, float& hi) {
    asm("mov.b64 {%0,%1},%2;" : "=f"(lo), "=f"(hi) : "l"(v));
}
__device__ __forceinline__ ull ffma2(ull a, ull b, ull c) {
    ull d; asm("fma.rn.f32x2 %0,%1,%2,%3;" : "=l"(d) : "l"(a), "l"(b), "l"(c));
    return d;
}

// ======================= split-bf16 tensor-core GEMM ========================
#define BM 128
#define BK 32
#define NSTG 3

__device__ __forceinline__ void ldm_x4(unsigned r[4], unsigned addr) {
    asm volatile("ldmatrix.sync.aligned.m8n8.x4.shared.b16 {%0,%1,%2,%3}, [%4];"
        : "=r"(r[0]), "=r"(r[1]), "=r"(r[2]), "=r"(r[3]) : "r"(addr));
}
__device__ __forceinline__ void mma16816(float c[4], const unsigned a[4],
                                         unsigned b0, unsigned b1) {
    asm volatile("mma.sync.aligned.m16n8k16.row.col.f32.bf16.bf16.f32 "
        "{%0,%1,%2,%3},{%4,%5,%6,%7},{%8,%9},{%0,%1,%2,%3};"
        : "+f"(c[0]), "+f"(c[1]), "+f"(c[2]), "+f"(c[3])
        : "r"(a[0]), "r"(a[1]), "r"(a[2]), "r"(a[3]), "r"(b0), "r"(b1));
}
__device__ __forceinline__ void cp16(unsigned saddr, const void* g) {
    asm volatile("cp.async.cg.shared.global [%0], [%1], 16;\n" :: "r"(saddr), "l"(g));
}

// C = alpha * A(M,K) x B(N,K)^T, split precision hh+hl+lh.
template <int BN_, int CJ, int CK, int OUT>
__global__ __launch_bounds__(256)
void hgemm_kernel(const bf16* __restrict__ Ahi, const bf16* __restrict__ Alo,
                  const bf16* __restrict__ Bhi, const bf16* __restrict__ Blo,
                  float* __restrict__ Cf, bf16* __restrict__ Chi, bf16* __restrict__ Clo,
                  int M, int N, int K, int lda, int ldb, int ldc,
                  long long sA, long long sB, long long sC, float alpha)
{
    constexpr int WCOL = BN_ / 4;
    constexpr int NT = WCOL / 16;
    constexpr unsigned BOFF = 16384u;
    constexpr unsigned BLO  = 16384u + BN_ * 64u;
    constexpr unsigned STG  = 16384u + BN_ * 128u;

    const int bz = blockIdx.z;
    Ahi += (long long)bz * sA;  Alo += (long long)bz * sA;
    Bhi += (long long)bz * sB;  Blo += (long long)bz * sB;

    const int bi = blockIdx.y * BM, bj = blockIdx.x * BN_;
    if (CJ && bj > bi + BM - 1) return;

    extern __shared__ bf16 smem[];
    const unsigned sgen = (unsigned)__cvta_generic_to_shared(smem);
    const int tid = threadIdx.x;
    const int wid = tid >> 5, lane = tid & 31;
    const int wm = wid >> 2, wn = wid & 3;

    float acc[4][2 * NT][4];
    #pragma unroll
    for (int a = 0; a < 4; a++)
        #pragma unroll
        for (int b = 0; b < 2 * NT; b++)
            #pragma unroll
            for (int c = 0; c < 4; c++) acc[a][b][c] = 0.f;

    const int kmax = CK ? (bi + BM < K ? bi + BM : K) : K;
    const int nkt = kmax / BK;

    auto load_stage = [&](int stage, int kt) {
        int k0 = kt * BK;
        unsigned sb = sgen + stage * STG;
        #pragma unroll
        for (int rep = 0; rep < 2; rep++) {
            int c = tid + rep * 256;
            int row = c >> 2, kc = c & 3;
            unsigned swc = (unsigned)(kc ^ ((row >> 1) & 3));
            unsigned so = sb + (unsigned)row * 64u + swc * 16u;
            cp16(so,         Ahi + (size_t)(bi + row) * lda + k0 + kc * 8);
            cp16(so + 8192u, Alo + (size_t)(bi + row) * lda + k0 + kc * 8);
        }
        #pragma unroll
        for (int rep = 0; rep < BN_ / 64; rep++) {
            int c = tid + rep * 256;
            int row = c >> 2, kc = c & 3;
            unsigned swc = (unsigned)(kc ^ ((row >> 1) & 3));
            unsigned so = sb + (unsigned)row * 64u + swc * 16u;
            cp16(so + BOFF, Bhi + (size_t)(bj + row) * ldb + k0 + kc * 8);
            cp16(so + BLO,  Blo + (size_t)(bj + row) * ldb + k0 + kc * 8);
        }
    };

    auto compute_stage = [&](int stage) {
        unsigned sb = sgen + stage * STG;
        #pragma unroll
        for (int ks = 0; ks < 2; ks++) {
            int r = lane & 15;
            int cc = ks * 2 + (lane >> 4);
            unsigned a_hi[4][4], a_lo[4][4];
            #pragma unroll
            for (int mt = 0; mt < 4; mt++) {
                int row = wm * 64 + mt * 16 + r;
                unsigned swc = (unsigned)(cc ^ ((row >> 1) & 3));
                unsigned addr = sb + (unsigned)row * 64u + swc * 16u;
                ldm_x4(a_hi[mt], addr);
                ldm_x4(a_lo[mt], addr + 8192u);
            }
            unsigned b_hi[NT][4], b_lo[NT][4];
            #pragma unroll
            for (int bt = 0; bt < NT; bt++) {
                int row = wn * WCOL + bt * 16 + r;
                unsigned swc = (unsigned)(cc ^ ((row >> 1) & 3));
                unsigned addr = sb + BOFF + (unsigned)row * 64u + swc * 16u;
                ldm_x4(b_hi[bt], addr);
                ldm_x4(b_lo[bt], addr + (BN_ * 64u));
            }
            #pragma unroll
            for (int mt = 0; mt < 4; mt++)
                #pragma unroll
                for (int n = 0; n < 2 * NT; n++) {
                    int bt = n >> 1, sel = n & 1;
                    unsigned b0h = b_hi[bt][sel], b1h = b_hi[bt][sel + 2];
                    unsigned b0l = b_lo[bt][sel], b1l = b_lo[bt][sel + 2];
                    mma16816(acc[mt][n], a_hi[mt], b0h, b1h);
                    mma16816(acc[mt][n], a_hi[mt], b0l, b1l);
                    mma16816(acc[mt][n], a_lo[mt], b0h, b1h);
                }
        }
    };

    #pragma unroll
    for (int s = 0; s < NSTG - 1; s++) {
        if (s < nkt) load_stage(s, s);
        asm volatile("cp.async.commit_group;\n");
    }
    for (int kt = 0; kt < nkt; kt++) {
        asm volatile("cp.async.wait_group %0;\n" :: "n"(NSTG - 2));
        __syncthreads();
        int kn = kt + NSTG - 1;
        if (kn < nkt) load_stage(kn % NSTG, kn);
        asm volatile("cp.async.commit_group;\n");
        compute_stage(kt % NSTG);
    }

    #pragma unroll
    for (int mt = 0; mt < 4; mt++) {
        int r0 = bi + wm * 64 + mt * 16 + (lane >> 2);
        #pragma unroll
        for (int n = 0; n < 2 * NT; n++) {
            int col = bj + wn * WCOL + (n >> 1) * 16 + (n & 1) * 8 + 2 * (lane & 3);
            if (OUT == 0) {
                float* C = Cf + (long long)bz * sC;
                float2 v0 = {alpha * acc[mt][n][0], alpha * acc[mt][n][1]};
                float2 v1 = {alpha * acc[mt][n][2], alpha * acc[mt][n][3]};
                *(float2*)&C[(size_t)r0 * ldc + col] = v0;
                *(float2*)&C[(size_t)(r0 + 8) * ldc + col] = v1;
            } else {
                long long base = (long long)(bz >> 4) * ((long long)Lq * HIDq)
                               + (long long)(bz & 15) * Dq;
                #pragma unroll
                for (int rr = 0; rr < 2; rr++) {
                    float va = acc[mt][n][rr * 2], vb = acc[mt][n][rr * 2 + 1];
                    bf16 ha = __float2bfloat16(va), hb = __float2bfloat16(vb);
                    bf16 la = __float2bfloat16(va - __bfloat162float(ha));
                    bf16 lb = __float2bfloat16(vb - __bfloat162float(hb));
                    size_t off = base + (size_t)(r0 + rr * 8) * ldc + col;
                    *(__nv_bfloat162*)&Chi[off] = __nv_bfloat162(ha, hb);
                    *(__nv_bfloat162*)&Clo[off] = __nv_bfloat162(la, lb);
                }
            }
        }
    }
}

// ---------------- fp32 -> bf16 hi/lo conversion kernels ----------------------
__global__ void conv_split_kernel(const float* __restrict__ src,
                                  bf16* __restrict__ hi, bf16* __restrict__ lo, int n)
{
    int i = blockIdx.x * blockDim.x + threadIdx.x;
    if (i >= n) return;
    float v = src[i];
    bf16 h = __float2bfloat16(v);
    hi[i] = h;
    lo[i] = __float2bfloat16(v - __bfloat162float(h));
}

__global__ void conv_split_trans_kernel(const float* __restrict__ W,
                                        bf16* __restrict__ hi, bf16* __restrict__ lo,
                                        int K, int N)
{
    __shared__ float t[32][33];
    int k0 = blockIdx.y * 32, n0 = blockIdx.x * 32;
    int tx = threadIdx.x, ty = threadIdx.y;
    #pragma unroll
    for (int r = ty; r < 32; r += 8)
        t[r][tx] = W[(size_t)(k0 + r) * N + n0 + tx];
    __syncthreads();
    #pragma unroll
    for (int r = ty; r < 32; r += 8) {
        float v = t[tx][r];
        bf16 h = __float2bfloat16(v);
        hi[(size_t)(n0 + r) * K + k0 + tx] = h;
        lo[(size_t)(n0 + r) * K + k0 + tx] = __float2bfloat16(v - __bfloat162float(h));
    }
}

// ---------------- qkv split + RoPE -> bf16 hi/lo (q,k) + transposed v -------
__global__ __launch_bounds__(256)
void rope_split_kernel(const float* __restrict__ qkv,
                       bf16* __restrict__ qhi, bf16* __restrict__ qlo,
                       bf16* __restrict__ khi, bf16* __restrict__ klo,
                       bf16* __restrict__ vThi, bf16* __restrict__ vTlo)
{
    __shared__ float sv[32][65];
    int bid = blockIdx.x;
    int l0 = (bid & 31) * 32;
    int h = (bid >> 5) & 15;
    int b = bid >> 9;
    int tid = threadIdx.x;

    #pragma unroll
    for (int e = 0; e < 8; e++) {
        int idx = tid + e * 256;
        int d = idx & 63, lr = idx >> 6;
        int l = l0 + lr;
        long long base = ((long long)(b * Lq + l) * 3) * (Hq * Dq) + h * Dq;
        float qa = qkv[base + d];
        float ka = qkv[base + Hq * Dq + d];
        float vv = qkv[base + 2 * Hq * Dq + d];
        int dp = (d < 32) ? d + 32 : d - 32;
        float qb = qkv[base + dp];
        float kb = qkv[base + Hq * Dq + dp];

        int fi = (d < 32) ? d : d - 32;
        float ang = (float)l * powf(10000.0f, -(float)fi / 32.0f);
        float c = cosf(ang), s = sinf(ang);
        float sgn = (d < 32) ? -1.0f : 1.0f;

        float qv = qa * c + sgn * qb * s;
        float kv = ka * c + sgn * kb * s;

        long long o = ((long long)(b * Hq + h) * Lq + l) * Dq + d;
        bf16 qh = __float2bfloat16(qv), kh = __float2bfloat16(kv);
        qhi[o] = qh; qlo[o] = __float2bfloat16(qv - __bfloat162float(qh));
        khi[o] = kh; klo[o] = __float2bfloat16(kv - __bfloat162float(kh));
        sv[lr][d] = vv;
    }
    __syncthreads();
    #pragma unroll
    for (int e = 0; e < 8; e++) {
        int idx = tid + e * 256;
        int lr = idx & 31, d = idx >> 5;
        float vv = sv[lr][d];
        bf16 vh = __float2bfloat16(vv);
        long long o = ((long long)(b * Hq + h) * Dq + d) * Lq + l0 + lr;
        vThi[o] = vh;
        vTlo[o] = __float2bfloat16(vv - __bfloat162float(vh));
    }
}

// ---------------- DAPE tables: kc[o][dist], ktab[h][dist] --------------------
__global__ void dape_pre_kernel(const float* __restrict__ w1, const float* __restrict__ b1,
                                const float* __restrict__ log_p, const float* __restrict__ log_a,
                                float* __restrict__ kc_t, float* __restrict__ ktab_t)
{
    int dist = blockIdx.x;
    int t = threadIdx.x;    // 32
    __shared__ float kv[16];
    if (t < 16) {
        float p = log1pf(expf(log_p[t]));
        float a = log1pf(expf(log_a[t]));
        float kvv = -p * log1pf(a * (float)dist);
        kv[t] = kvv;
        ktab_t[t * 1024 + dist] = kvv;
    }
    __syncthreads();
    float acc = b1[t];
    #pragma unroll
    for (int h = 0; h < 16; h++) acc += kv[h] * w1[(16 + h) * 32 + t];
    kc_t[t * 1024 + dist] = acc;
}

// ---------------- fused DAPE MLP + kerple + causal softmax (f32x2) ----------
// One block per (b,i), 1024 threads, 1 j per thread. Emits bf16 hi/lo weights.
__global__ __launch_bounds__(1024, 1)
void dape_softmax_kernel(const float* __restrict__ scores,
                         bf16* __restrict__ whi, bf16* __restrict__ wlo,
                         const float* __restrict__ w1, const float* __restrict__ w2,
                         const float* __restrict__ b2,
                         const float* __restrict__ kc_t, const float* __restrict__ ktab_t)
{
    __shared__ ull s_w1p[32 * 8];   // [o][p] pairs over input h: (w1[2p][o], w1[2p+1][o])
    __shared__ ull s_w2p[32 * 8];   // [o][p] pairs over out  h: (w2[o][2p], w2[o][2p+1])
    __shared__ float s_b2[16];
    __shared__ float s_red[16 * 32];
    __shared__ float s_bc[16];

    int tid = threadIdx.x;
    int i = blockIdx.x & (Lq - 1);
    int b = blockIdx.x >> 10;

    if (tid < 256) {
        int o = tid >> 3, p = tid & 7;
        s_w1p[o * 8 + p] = pk2(w1[(2 * p) * 32 + o], w1[(2 * p + 1) * 32 + o]);
        s_w2p[o * 8 + p] = pk2(w2[o * 16 + 2 * p], w2[o * 16 + 2 * p + 1]);
    }
    if (tid < 16) s_b2[tid] = b2[tid];
    __syncthreads();

    long long base0 = (long long)b * (Hq * Lq * Lq) + (long long)i * Lq;
    int j = tid;
    ull out2[8];

    if (j <= i) {
        int dist = i - j;
        ull s2[8];
        #pragma unroll
        for (int p = 0; p < 8; p++) {
            float s0 = scores[base0 + (long long)(2 * p)     * (Lq * Lq) + j];
            float s1 = scores[base0 + (long long)(2 * p + 1) * (Lq * Lq) + j];
            s2[p] = pk2(s0, s1);
            float k0 = ktab_t[(2 * p) * 1024 + dist];
            float k1 = ktab_t[(2 * p + 1) * 1024 + dist];
            out2[p] = pk2(s0 + k0 + s_b2[2 * p], s1 + k1 + s_b2[2 * p + 1]);
        }
        #pragma unroll 4
        for (int o = 0; o < 32; o++) {
            ull acc2 = pk2(kc_t[o * 1024 + dist], 0.0f);
            #pragma unroll
            for (int p = 0; p < 8; p++) acc2 = ffma2(s2[p], s_w1p[o * 8 + p], acc2);
            float a0, a1; upk2(acc2, a0, a1);
            float acc = a0 + a1;
            float g = 0.5f * acc * (1.0f + erff(acc * 0.70710678118654752f));
            ull g2 = pk2(g, g);
            #pragma unroll
            for (int p = 0; p < 8; p++) out2[p] = ffma2(g2, s_w2p[o * 8 + p], out2[p]);
        }
    } else {
        #pragma unroll
        for (int p = 0; p < 8; p++) out2[p] = pk2(-INFINITY, -INFINITY);
    }

    int warp = tid >> 5, ln = tid & 31;

    // per-head block max
    #pragma unroll
    for (int p = 0; p < 8; p++) {
        float v0, v1; upk2(out2[p], v0, v1);
        #pragma unroll
        for (int off = 16; off > 0; off >>= 1) {
            v0 = fmaxf(v0, __shfl_xor_sync(0xffffffffu, v0, off));
            v1 = fmaxf(v1, __shfl_xor_sync(0xffffffffu, v1, off));
        }
        if (ln == 0) { s_red[(2 * p) * 32 + warp] = v0; s_red[(2 * p + 1) * 32 + warp] = v1; }
    }
    __syncthreads();
    if (tid < 16) {
        float v = s_red[tid * 32];
        #pragma unroll
        for (int w = 1; w < 32; w++) v = fmaxf(v, s_red[tid * 32 + w]);
        s_bc[tid] = v;
    }
    __syncthreads();

    // exp (reads max from smem; no mx[] registers) + per-head sum
    #pragma unroll
    for (int p = 0; p < 8; p++) {
        float v0, v1; upk2(out2[p], v0, v1);
        v0 = __expf(v0 - s_bc[2 * p]);        // __expf(-inf)=0 for masked j
        v1 = __expf(v1 - s_bc[2 * p + 1]);
        out2[p] = pk2(v0, v1);
    }
    __syncthreads();
    #pragma unroll
    for (int p = 0; p < 8; p++) {
        float v0, v1; upk2(out2[p], v0, v1);
        #pragma unroll
        for (int off = 16; off > 0; off >>= 1) {
            v0 += __shfl_xor_sync(0xffffffffu, v0, off);
            v1 += __shfl_xor_sync(0xffffffffu, v1, off);
        }
        if (ln == 0) { s_red[(2 * p) * 32 + warp] = v0; s_red[(2 * p + 1) * 32 + warp] = v1; }
    }
    __syncthreads();
    if (tid < 16) {
        float v = 0.0f;
        #pragma unroll
        for (int w = 0; w < 32; w++) v += s_red[tid * 32 + w];
        s_bc[tid] = 1.0f / v;
    }
    __syncthreads();

    #pragma unroll
    for (int p = 0; p < 8; p++) {
        float v0, v1; upk2(out2[p], v0, v1);
        float w0 = v0 * s_bc[2 * p];
        float w1v = v1 * s_bc[2 * p + 1];
        bf16 h0 = __float2bfloat16(w0);
        bf16 h1 = __float2bfloat16(w1v);
        long long off0 = base0 + (long long)(2 * p) * (Lq * Lq) + j;
        long long off1 = base0 + (long long)(2 * p + 1) * (Lq * Lq) + j;
        whi[off0] = h0; wlo[off0] = __float2bfloat16(w0 - __bfloat162float(h0));
        whi[off1] = h1; wlo[off1] = __float2bfloat16(w1v - __bfloat162float(h1));
    }
}

// ---------------- launch ----------------------------------------------------
extern "C" void kernel_launch(void* const* d_in, const int* in_sizes, int n_in,
                              void* d_out, int out_size)
{
    const float* x     = (const float*)d_in[0];
    const float* w_qkv = (const float*)d_in[1];
    const float* w_o   = (const float*)d_in[2];
    const float* log_p = (const float*)d_in[3];
    const float* log_a = (const float*)d_in[4];
    const float* w1    = (const float*)d_in[5];
    const float* b1    = (const float*)d_in[6];
    const float* w2    = (const float*)d_in[7];
    const float* b2    = (const float*)d_in[8];
    float* out = (float*)d_out;
    (void)in_sizes; (void)n_in; (void)out_size;

    float *qkv, *sc, *kc, *ktab;
    bf16 *qhi, *qlo, *khi, *klo, *vThi, *vTlo, *whi, *wlo;
    bf16 *xhi, *xlo, *wqT_hi, *wqT_lo, *attnhi, *attnlo, *woT_hi, *woT_lo;
    cudaGetSymbolAddress((void**)&qkv,  g_qkv);
    cudaGetSymbolAddress((void**)&sc,   g_sc);
    cudaGetSymbolAddress((void**)&kc,   g_kc);
    cudaGetSymbolAddress((void**)&ktab, g_ktab);
    cudaGetSymbolAddress((void**)&qhi,  g_qhi);
    cudaGetSymbolAddress((void**)&qlo,  g_qlo);
    cudaGetSymbolAddress((void**)&khi,  g_khi);
    cudaGetSymbolAddress((void**)&klo,  g_klo);
    cudaGetSymbolAddress((void**)&vThi, g_vThi);
    cudaGetSymbolAddress((void**)&vTlo, g_vTlo);
    cudaGetSymbolAddress((void**)&whi,  g_whi);
    cudaGetSymbolAddress((void**)&wlo,  g_wlo);
    cudaGetSymbolAddress((void**)&xhi,    g_xhi);
    cudaGetSymbolAddress((void**)&xlo,    g_xlo);
    cudaGetSymbolAddress((void**)&wqT_hi, g_wqkvT_hi);
    cudaGetSymbolAddress((void**)&wqT_lo, g_wqkvT_lo);
    cudaGetSymbolAddress((void**)&attnhi, g_attnhi);
    cudaGetSymbolAddress((void**)&attnlo, g_attnlo);
    cudaGetSymbolAddress((void**)&woT_hi, g_woT_hi);
    cudaGetSymbolAddress((void**)&woT_lo, g_woT_lo);

    static int smem_set = 0;
    if (!smem_set) {
        cudaFuncSetAttribute(hgemm_kernel<128, 0, 0, 0>,
                             cudaFuncAttributeMaxDynamicSharedMemorySize, 3 * 32768);
        cudaFuncSetAttribute(hgemm_kernel<128, 1, 0, 0>,
                             cudaFuncAttributeMaxDynamicSharedMemorySize, 3 * 32768);
        cudaFuncSetAttribute(hgemm_kernel<64, 0, 1, 1>,
                             cudaFuncAttributeMaxDynamicSharedMemorySize, 3 * 24576);
        smem_set = 1;
    }

    const int M = Bq * Lq;           // 2048
    const int TH = 3 * Hq * Dq;      // 3072

    // 0) DAPE tables
    dape_pre_kernel<<<1024, 32>>>(w1, b1, log_p, log_a, kc, ktab);

    // 1) conversions for qkv GEMM
    conv_split_kernel<<<(M * HIDq) / 256, 256>>>(x, xhi, xlo, M * HIDq);
    conv_split_trans_kernel<<<dim3(TH / 32, HIDq / 32), dim3(32, 8)>>>(
        w_qkv, wqT_hi, wqT_lo, HIDq, TH);

    // 2) qkv = x @ w_qkv (tensor cores)
    hgemm_kernel<128, 0, 0, 0><<<dim3(TH / 128, M / 128), 256, 3 * 32768>>>(
        xhi, xlo, wqT_hi, wqT_lo, qkv, nullptr, nullptr,
        M, TH, HIDq, HIDq, HIDq, TH, 0, 0, 0, 1.0f);

    // 3) split + RoPE -> bf16 hi/lo q,k + transposed v
    rope_split_kernel<<<Bq * Hq * (Lq / 32), 256>>>(qkv, qhi, qlo, khi, klo, vThi, vTlo);

    // 4) scores = (q @ k^T)/8, batched 32, causal tile skip (tensor cores)
    hgemm_kernel<128, 1, 0, 0><<<dim3(Lq / 128, Lq / 128, Bq * Hq), 256, 3 * 32768>>>(
        qhi, qlo, khi, klo, sc, nullptr, nullptr,
        Lq, Lq, Dq, Dq, Dq, Lq,
        (long long)Lq * Dq, (long long)Lq * Dq, (long long)Lq * Lq, 0.125f);

    // 5) fused kerple + DAPE MLP + causal softmax -> bf16 hi/lo weights
    dape_softmax_kernel<<<Bq * Lq, 1024>>>(sc, whi, wlo, w1, w2, b2, kc, ktab);

    // 6) attn = weights @ v (tensor cores, causal-K, bf16 hi/lo out in (B,L,H*D))
    hgemm_kernel<64, 0, 1, 1><<<dim3(1, Lq / 128, Bq * Hq), 256, 3 * 24576>>>(
        whi, wlo, vThi, vTlo, nullptr, attnhi, attnlo,
        Lq, Dq, Lq, Lq, Lq, HIDq,
        (long long)Lq * Lq, (long long)Dq * Lq, 0, 1.0f);

    // 7) out = attn @ w_o (tensor cores)
    conv_split_trans_kernel<<<dim3(HIDq / 32, HIDq / 32), dim3(32, 8)>>>(
        w_o, woT_hi, woT_lo, HIDq, HIDq);
    hgemm_kernel<128, 0, 0, 0><<<dim3(HIDq / 128, M / 128), 256, 3 * 32768>>>(
        attnhi, attnlo, woT_hi, woT_lo, out, nullptr, nullptr,
        M, HIDq, HIDq, HIDq, HIDq, HIDq, 0, 0, 0, 1.0f);
}